// round 1
// baseline (speedup 1.0000x reference)
#include <cuda_runtime.h>
#include <cuda_bf16.h>
#include <math.h>

#define B_ 2
#define S_ 2048
#define E_ 512
#define H_ 8
#define DH_ 64
#define SCALE_ 0.125f  // 64^-0.5

#define BM 64
#define BN 64
#define BK 16

// ---- scratch (device globals; allocation is forbidden) ----
__device__ float g_Q[B_ * H_ * S_ * DH_];   // [b][h][s][d]
__device__ float g_K[B_ * H_ * S_ * DH_];
__device__ float g_V[B_ * H_ * S_ * DH_];
__device__ float g_ctx[B_ * S_ * E_];       // [b][s][h*DH+d]
__device__ float g_tw[S_ * S_];             // exp(-layer_distances)

// ---------------------------------------------------------------------------
// exp(-distance) precompute
// ---------------------------------------------------------------------------
__global__ void tw_kernel(const float* __restrict__ ld) {
    int i = blockIdx.x * blockDim.x + threadIdx.x;
    if (i < S_ * S_) g_tw[i] = expf(-ld[i]);
}

// ---------------------------------------------------------------------------
// Y = X @ W^T + bias.  X:[M,K] row-major, W:[N,K] row-major.
// mode 0: scatter to [b][h][s][d] head layout (M = B*S, N = E)
// mode 1: plain row-major [M,N]
// M % 64 == 0, N % 64 == 0, K % 16 == 0 (all true here).
// ---------------------------------------------------------------------------
__global__ void gemm_wt_kernel(const float* __restrict__ A,
                               const float* __restrict__ W,
                               const float* __restrict__ bias,
                               float* __restrict__ out,
                               int M, int N, int K, int mode) {
    __shared__ float As[BK][BM + 1];
    __shared__ float Ws[BK][BN + 1];
    const int tid = threadIdx.x;            // 256 threads
    const int tx = tid & 15, ty = tid >> 4;
    const int m0 = blockIdx.y * BM, n0 = blockIdx.x * BN;

    float acc[4][4] = {};
    for (int k0 = 0; k0 < K; k0 += BK) {
        #pragma unroll
        for (int i = 0; i < 4; i++) {
            int idx = tid + i * 256;        // 1024 elements = 64 rows x 16 k
            int r = idx >> 4, c = idx & 15;
            As[c][r] = A[(size_t)(m0 + r) * K + k0 + c];
            Ws[c][r] = W[(size_t)(n0 + r) * K + k0 + c];
        }
        __syncthreads();
        #pragma unroll
        for (int kk = 0; kk < BK; kk++) {
            float a[4], w[4];
            #pragma unroll
            for (int i = 0; i < 4; i++) a[i] = As[kk][ty * 4 + i];
            #pragma unroll
            for (int j = 0; j < 4; j++) w[j] = Ws[kk][tx * 4 + j];
            #pragma unroll
            for (int i = 0; i < 4; i++)
                #pragma unroll
                for (int j = 0; j < 4; j++) acc[i][j] += a[i] * w[j];
        }
        __syncthreads();
    }

    #pragma unroll
    for (int i = 0; i < 4; i++) {
        int m = m0 + ty * 4 + i;
        #pragma unroll
        for (int j = 0; j < 4; j++) {
            int n = n0 + tx * 4 + j;
            float v = acc[i][j] + bias[n];
            if (mode == 0) {
                int b = m / S_, s = m % S_;
                int h = n / DH_, d = n % DH_;
                out[(((size_t)b * H_ + h) * S_ + s) * DH_ + d] = v;
            } else {
                out[(size_t)m * N + n] = v;
            }
        }
    }
}

// ---------------------------------------------------------------------------
// scores[bh, m, n] = (q[bh,m,:] . k[bh,n,:]) * SCALE + tbias[h]*tw[m,n], masked
// grid: (S/64, S/64, B*H), block 256
// ---------------------------------------------------------------------------
__global__ void scores_kernel(const int* __restrict__ mask,
                              const float* __restrict__ tbias,
                              float* __restrict__ P) {
    __shared__ float Qs[BK][BM + 1];
    __shared__ float Ks[BK][BN + 1];
    const int tid = threadIdx.x;
    const int tx = tid & 15, ty = tid >> 4;
    const int bh = blockIdx.z;
    const int h = bh % H_;
    const float* q = g_Q + (size_t)bh * S_ * DH_;
    const float* k = g_K + (size_t)bh * S_ * DH_;
    const int m0 = blockIdx.y * BM, n0 = blockIdx.x * BN;

    float acc[4][4] = {};
    #pragma unroll
    for (int k0 = 0; k0 < DH_; k0 += BK) {
        #pragma unroll
        for (int i = 0; i < 4; i++) {
            int idx = tid + i * 256;
            int r = idx >> 4, c = idx & 15;
            Qs[c][r] = q[(size_t)(m0 + r) * DH_ + k0 + c];
            Ks[c][r] = k[(size_t)(n0 + r) * DH_ + k0 + c];
        }
        __syncthreads();
        #pragma unroll
        for (int kk = 0; kk < BK; kk++) {
            float a[4], w[4];
            #pragma unroll
            for (int i = 0; i < 4; i++) a[i] = Qs[kk][ty * 4 + i];
            #pragma unroll
            for (int j = 0; j < 4; j++) w[j] = Ks[kk][tx * 4 + j];
            #pragma unroll
            for (int i = 0; i < 4; i++)
                #pragma unroll
                for (int j = 0; j < 4; j++) acc[i][j] += a[i] * w[j];
        }
        __syncthreads();
    }

    const float hb = tbias[h];
    float* prow = P + (size_t)bh * S_ * S_;
    #pragma unroll
    for (int i = 0; i < 4; i++) {
        int m = m0 + ty * 4 + i;
        #pragma unroll
        for (int j = 0; j < 4; j++) {
            int n = n0 + tx * 4 + j;
            size_t mn = (size_t)m * S_ + n;
            float s = acc[i][j] * SCALE_ + hb * g_tw[mn];
            if (mask[mn] == 0) s = -1e9f;
            prow[mn] = s;
        }
    }
}

// ---------------------------------------------------------------------------
// in-place row softmax over the last S_ dim.  one block per row.
// ---------------------------------------------------------------------------
__global__ void softmax_kernel(float* __restrict__ P) {
    const int tid = threadIdx.x;          // 256
    float* p = P + (size_t)blockIdx.x * S_;
    __shared__ float red[256];

    float x[8];
    float mx = -INFINITY;
    #pragma unroll
    for (int i = 0; i < 8; i++) {
        x[i] = p[tid + i * 256];
        mx = fmaxf(mx, x[i]);
    }
    red[tid] = mx;
    __syncthreads();
    for (int s = 128; s > 0; s >>= 1) {
        if (tid < s) red[tid] = fmaxf(red[tid], red[tid + s]);
        __syncthreads();
    }
    mx = red[0];
    __syncthreads();

    float sum = 0.f;
    #pragma unroll
    for (int i = 0; i < 8; i++) {
        x[i] = expf(x[i] - mx);
        sum += x[i];
    }
    red[tid] = sum;
    __syncthreads();
    for (int s = 128; s > 0; s >>= 1) {
        if (tid < s) red[tid] += red[tid + s];
        __syncthreads();
    }
    float inv = 1.0f / red[0];
    #pragma unroll
    for (int i = 0; i < 8; i++) p[tid + i * 256] = x[i] * inv;
}

// ---------------------------------------------------------------------------
// ctx[b, m, h*DH+d] = sum_k P[bh,m,k] * V[bh,k,d]
// grid: (1, S/64, B*H), block 256.  N tile = DH_ = 64.
// ---------------------------------------------------------------------------
__global__ void ctx_kernel(const float* __restrict__ P) {
    __shared__ float Ps[BK][BM + 1];
    __shared__ float Vs[BK][DH_ + 1];
    const int tid = threadIdx.x;
    const int tx = tid & 15, ty = tid >> 4;
    const int bh = blockIdx.z;
    const int b = bh / H_, h = bh % H_;
    const float* p = P + (size_t)bh * S_ * S_;
    const float* v = g_V + (size_t)bh * S_ * DH_;
    const int m0 = blockIdx.y * BM;

    float acc[4][4] = {};
    for (int k0 = 0; k0 < S_; k0 += BK) {
        #pragma unroll
        for (int i = 0; i < 4; i++) {
            int idx = tid + i * 256;
            // P tile: 64 rows x 16 k
            int r = idx >> 4, c = idx & 15;
            Ps[c][r] = p[(size_t)(m0 + r) * S_ + k0 + c];
            // V tile: 16 k-rows x 64 d-cols (coalesced on d)
            int vr = idx >> 6, vc = idx & 63;
            Vs[vr][vc] = v[(size_t)(k0 + vr) * DH_ + vc];
        }
        __syncthreads();
        #pragma unroll
        for (int kk = 0; kk < BK; kk++) {
            float a[4], w[4];
            #pragma unroll
            for (int i = 0; i < 4; i++) a[i] = Ps[kk][ty * 4 + i];
            #pragma unroll
            for (int j = 0; j < 4; j++) w[j] = Vs[kk][tx * 4 + j];
            #pragma unroll
            for (int i = 0; i < 4; i++)
                #pragma unroll
                for (int j = 0; j < 4; j++) acc[i][j] += a[i] * w[j];
        }
        __syncthreads();
    }

    #pragma unroll
    for (int i = 0; i < 4; i++) {
        int m = m0 + ty * 4 + i;
        #pragma unroll
        for (int j = 0; j < 4; j++) {
            int d = tx * 4 + j;
            g_ctx[((size_t)b * S_ + m) * E_ + h * DH_ + d] = acc[i][j];
        }
    }
}

// ---------------------------------------------------------------------------
extern "C" void kernel_launch(void* const* d_in, const int* in_sizes, int n_in,
                              void* d_out, int out_size) {
    const float* query = (const float*)d_in[0];
    const float* key   = (const float*)d_in[1];
    const float* value = (const float*)d_in[2];
    const int*   tmask = (const int*)d_in[3];
    const float* ldist = (const float*)d_in[4];
    const float* Wq = (const float*)d_in[5];
    const float* bq = (const float*)d_in[6];
    const float* Wk = (const float*)d_in[7];
    const float* bk = (const float*)d_in[8];
    const float* Wv = (const float*)d_in[9];
    const float* bv = (const float*)d_in[10];
    const float* Wo = (const float*)d_in[11];
    const float* bo = (const float*)d_in[12];
    const float* tbias = (const float*)d_in[13];

    float* out_attn  = (float*)d_out;                       // [B,S,E]
    float* out_probs = (float*)d_out + (size_t)B_ * S_ * E_; // [B,H,S,S]

    float* qg; cudaGetSymbolAddress((void**)&qg, g_Q);
    float* kg; cudaGetSymbolAddress((void**)&kg, g_K);
    float* vg; cudaGetSymbolAddress((void**)&vg, g_V);
    float* cg; cudaGetSymbolAddress((void**)&cg, g_ctx);

    const int M = B_ * S_;   // 4096

    // exp(-distance)
    tw_kernel<<<(S_ * S_ + 255) / 256, 256>>>(ldist);

    // projections -> head layout
    dim3 gp(E_ / BN, M / BM);
    gemm_wt_kernel<<<gp, 256>>>(query, Wq, bq, qg, M, E_, E_, 0);
    gemm_wt_kernel<<<gp, 256>>>(key,   Wk, bk, kg, M, E_, E_, 0);
    gemm_wt_kernel<<<gp, 256>>>(value, Wv, bv, vg, M, E_, E_, 0);

    // scores + bias + mask -> probs buffer
    dim3 gs(S_ / BN, S_ / BM, B_ * H_);
    scores_kernel<<<gs, 256>>>(tmask, tbias, out_probs);

    // softmax in place
    softmax_kernel<<<B_ * H_ * S_, 256>>>(out_probs);

    // context = P @ V
    dim3 gc(1, S_ / BM, B_ * H_);
    ctx_kernel<<<gc, 256>>>(out_probs);

    // output projection
    gemm_wt_kernel<<<gp, 256>>>(cg, Wo, bo, out_attn, M, E_, E_, 1);
}

// round 2
// speedup vs baseline: 1.3551x; 1.3551x over previous
#include <cuda_runtime.h>
#include <cuda_bf16.h>
#include <math.h>
#include <stdint.h>

#define B_ 2
#define S_ 2048
#define E_ 512
#define H_ 8
#define DH_ 64
#define SCALE_ 0.125f  // 64^-0.5

#define BK 32          // fp32 k per mainloop iter
#define SK 72          // smem row stride in bf16 (64 data [hi|lo] + 8 pad) = 144B = 9*16B (odd -> LDSM conflict-free)

// ---- scratch (device globals; allocation is forbidden) ----
__device__ float g_Q[B_ * H_ * S_ * DH_];    // [bh][s][d]
__device__ float g_K[B_ * H_ * S_ * DH_];    // [bh][s][d]
__device__ float g_Vt[B_ * H_ * DH_ * S_];   // [bh][d][s]  (transposed V)
__device__ float g_ctx[B_ * S_ * E_];        // [b][s][h*DH+d]
__device__ float g_tw[S_ * S_];              // exp(-layer_distances)

// ---------------------------------------------------------------------------
__global__ void tw_kernel(const float* __restrict__ ld) {
    int i = blockIdx.x * blockDim.x + threadIdx.x;
    if (i < S_ * S_) g_tw[i] = expf(-ld[i]);
}

// ---------------------------------------------------------------------------
__device__ __forceinline__ void ldsm4(uint32_t addr, uint32_t& r0, uint32_t& r1,
                                      uint32_t& r2, uint32_t& r3) {
    asm volatile("ldmatrix.sync.aligned.m8n8.x4.shared.b16 {%0,%1,%2,%3}, [%4];"
                 : "=r"(r0), "=r"(r1), "=r"(r2), "=r"(r3) : "r"(addr));
}

__device__ __forceinline__ void mma16816(float* c, const uint32_t* a, const uint32_t* b) {
    asm volatile(
        "mma.sync.aligned.m16n8k16.row.col.f32.bf16.bf16.f32 "
        "{%0,%1,%2,%3}, {%4,%5,%6,%7}, {%8,%9}, {%0,%1,%2,%3};\n"
        : "+f"(c[0]), "+f"(c[1]), "+f"(c[2]), "+f"(c[3])
        : "r"(a[0]), "r"(a[1]), "r"(a[2]), "r"(a[3]), "r"(b[0]), "r"(b[1]));
}

// Fill a [ROWS x 32] fp32 tile into smem as bf16 [hi(0..31) | lo(32..63)] per row.
template <int ROWS>
__device__ __forceinline__ void fill_tile(const float* __restrict__ g, int ld,
                                          __nv_bfloat16* __restrict__ s, int tid) {
    constexpr int N4 = ROWS * BK / 4;
    #pragma unroll
    for (int i = 0; i < N4 / 256; i++) {
        int idx = tid + i * 256;
        int r = idx >> 3;           // BK/4 = 8 float4 per row
        int kc = (idx & 7) * 4;
        float4 v = *(const float4*)(g + (size_t)r * ld + kc);
        __nv_bfloat16 h0 = __float2bfloat16(v.x);
        __nv_bfloat16 h1 = __float2bfloat16(v.y);
        __nv_bfloat16 h2 = __float2bfloat16(v.z);
        __nv_bfloat16 h3 = __float2bfloat16(v.w);
        __nv_bfloat16 l0 = __float2bfloat16(v.x - __bfloat162float(h0));
        __nv_bfloat16 l1 = __float2bfloat16(v.y - __bfloat162float(h1));
        __nv_bfloat16 l2 = __float2bfloat16(v.z - __bfloat162float(h2));
        __nv_bfloat16 l3 = __float2bfloat16(v.w - __bfloat162float(h3));
        __nv_bfloat162* ph = (__nv_bfloat162*)(s + r * SK + kc);
        ph[0] = __halves2bfloat162(h0, h1);
        ph[1] = __halves2bfloat162(h2, h3);
        __nv_bfloat162* pl = (__nv_bfloat162*)(s + r * SK + 32 + kc);
        pl[0] = __halves2bfloat162(l0, l1);
        pl[1] = __halves2bfloat162(l2, l3);
    }
}

// ---------------------------------------------------------------------------
// D[M,N] = A[M,K] . B[N,K]^T in 3xBF16 (hi*hi + hi*lo + lo*hi), fp32 accumulate.
// MODE 0: out = head-layout scatter [bh][s][d] (+bias)       (Q/K projections)
// MODE 3: out = transposed head scatter [bh][d][s] (+bias)   (V projection)
// MODE 1: out = plain row-major [M,512] (+bias)              (output projection)
// MODE 2: scores epilogue: *SCALE + tbias[h]*tw, mask, write to P[bz]
// MODE 4: ctx epilogue: write g_ctx[b][m][h*64+n]
// ---------------------------------------------------------------------------
template <int WARPS_M, int WARPS_N, int BM, int BN, int MODE>
__global__ __launch_bounds__(256) void k_mm(
    const float* __restrict__ A, const float* __restrict__ B,
    const float* __restrict__ bias, float* __restrict__ out,
    int K, int lda, int ldb, long long sAz, long long sBz,
    const int* __restrict__ mask, const float* __restrict__ tbias) {
    constexpr int WM = BM / WARPS_M;
    constexpr int WN = BN / WARPS_N;
    constexpr int MF = WM / 16;
    constexpr int NF = WN / 8;

    __shared__ __nv_bfloat16 As[BM * SK];
    __shared__ __nv_bfloat16 Bs[BN * SK];

    const int tid = threadIdx.x, wid = tid >> 5, lane = tid & 31;
    const int wm = wid % WARPS_M, wn = wid / WARPS_M;
    const int bz = blockIdx.z;
    const int m0 = blockIdx.y * BM, n0 = blockIdx.x * BN;

    const float* Ap = A + (long long)bz * sAz + (size_t)m0 * lda;
    const float* Bp = B + (long long)bz * sBz + (size_t)n0 * ldb;

    float acc[MF][NF][4];
    #pragma unroll
    for (int i = 0; i < MF; i++)
        #pragma unroll
        for (int j = 0; j < NF; j++)
            #pragma unroll
            for (int q = 0; q < 4; q++) acc[i][j][q] = 0.f;

    uint32_t sA = (uint32_t)__cvta_generic_to_shared(As);
    uint32_t sB = (uint32_t)__cvta_generic_to_shared(Bs);
    const int t8 = lane >> 3, r8 = lane & 7;
    const int frow = r8 + 8 * (t8 & 1);
    const int fcol = 8 * (t8 >> 1);

    for (int k0 = 0; k0 < K; k0 += BK) {
        fill_tile<BM>(Ap + k0, lda, As, tid);
        fill_tile<BN>(Bp + k0, ldb, Bs, tid);
        __syncthreads();
        #pragma unroll
        for (int p = 0; p < 3; p++) {
            const int ao = (p == 2) ? 32 : 0;
            const int bo = (p == 1) ? 32 : 0;
            #pragma unroll
            for (int ks = 0; ks < 32; ks += 16) {
                uint32_t af[MF][4], bf[NF][2];
                #pragma unroll
                for (int mf = 0; mf < MF; mf++) {
                    uint32_t addr = sA + ((wm * WM + mf * 16 + frow) * SK + ao + ks + fcol) * 2;
                    ldsm4(addr, af[mf][0], af[mf][1], af[mf][2], af[mf][3]);
                }
                #pragma unroll
                for (int nf2 = 0; nf2 < NF / 2; nf2++) {
                    uint32_t r0, r1, r2, r3;
                    uint32_t addr = sB + ((wn * WN + nf2 * 16 + frow) * SK + bo + ks + fcol) * 2;
                    ldsm4(addr, r0, r1, r2, r3);
                    bf[2 * nf2][0] = r0;  bf[2 * nf2][1] = r2;
                    bf[2 * nf2 + 1][0] = r1;  bf[2 * nf2 + 1][1] = r3;
                }
                #pragma unroll
                for (int mf = 0; mf < MF; mf++)
                    #pragma unroll
                    for (int nf = 0; nf < NF; nf++)
                        mma16816(acc[mf][nf], af[mf], bf[nf]);
            }
        }
        __syncthreads();
    }

    // ---- epilogue ----
    const int lrow = lane >> 2, lcol = (lane & 3) * 2;
    #pragma unroll
    for (int mf = 0; mf < MF; mf++) {
        #pragma unroll
        for (int nf = 0; nf < NF; nf++) {
            #pragma unroll
            for (int hh = 0; hh < 2; hh++) {
                int m = m0 + wm * WM + mf * 16 + lrow + hh * 8;
                int n = n0 + wn * WN + nf * 8 + lcol;
                float v0 = acc[mf][nf][2 * hh];
                float v1 = acc[mf][nf][2 * hh + 1];
                if (MODE == 0) {  // head-layout scatter [bh][s][d]
                    int b = m >> 11, s = m & 2047;
                    int h = n >> 6, d = n & 63;
                    float2 val = make_float2(v0 + bias[n], v1 + bias[n + 1]);
                    *(float2*)&out[(((size_t)(b * H_ + h) * S_ + s) << 6) + d] = val;
                } else if (MODE == 3) {  // transposed V scatter [bh][d][s]
                    int b = m >> 11, s = m & 2047;
                    int h = n >> 6, d = n & 63;
                    size_t base = (size_t)(b * H_ + h) * DH_;
                    out[(base + d) * S_ + s] = v0 + bias[n];
                    out[(base + d + 1) * S_ + s] = v1 + bias[n + 1];
                } else if (MODE == 1) {  // plain [M,512]
                    float2 val = make_float2(v0 + bias[n], v1 + bias[n + 1]);
                    *(float2*)&out[(size_t)m * 512 + n] = val;
                } else if (MODE == 2) {  // scores
                    int h = bz & 7;
                    float tb = tbias[h];
                    size_t mn = (size_t)m * S_ + n;
                    float2 tw = *(const float2*)&g_tw[mn];
                    int2 mk = *(const int2*)&mask[mn];
                    float s0 = v0 * SCALE_ + tb * tw.x;
                    float s1 = v1 * SCALE_ + tb * tw.y;
                    if (mk.x == 0) s0 = -1e9f;
                    if (mk.y == 0) s1 = -1e9f;
                    *(float2*)&out[(size_t)bz * S_ * S_ + mn] = make_float2(s0, s1);
                } else {  // MODE 4: ctx
                    int b = bz >> 3, h = bz & 7;
                    *(float2*)&out[((size_t)b * S_ + m) * E_ + h * DH_ + n] =
                        make_float2(v0, v1);
                }
            }
        }
    }
}

// ---------------------------------------------------------------------------
// in-place row softmax, one block per row
// ---------------------------------------------------------------------------
__global__ void softmax_kernel(float* __restrict__ P) {
    const int tid = threadIdx.x;  // 256
    float* p = P + (size_t)blockIdx.x * S_;
    __shared__ float red[256];

    float x[8];
    float mx = -INFINITY;
    #pragma unroll
    for (int i = 0; i < 8; i++) {
        x[i] = p[tid + i * 256];
        mx = fmaxf(mx, x[i]);
    }
    red[tid] = mx;
    __syncthreads();
    for (int s = 128; s > 0; s >>= 1) {
        if (tid < s) red[tid] = fmaxf(red[tid], red[tid + s]);
        __syncthreads();
    }
    mx = red[0];
    __syncthreads();

    float sum = 0.f;
    #pragma unroll
    for (int i = 0; i < 8; i++) {
        x[i] = expf(x[i] - mx);
        sum += x[i];
    }
    red[tid] = sum;
    __syncthreads();
    for (int s = 128; s > 0; s >>= 1) {
        if (tid < s) red[tid] += red[tid + s];
        __syncthreads();
    }
    float inv = 1.0f / red[0];
    #pragma unroll
    for (int i = 0; i < 8; i++) p[tid + i * 256] = x[i] * inv;
}

// ---------------------------------------------------------------------------
extern "C" void kernel_launch(void* const* d_in, const int* in_sizes, int n_in,
                              void* d_out, int out_size) {
    const float* query = (const float*)d_in[0];
    const float* key   = (const float*)d_in[1];
    const float* value = (const float*)d_in[2];
    const int*   tmask = (const int*)d_in[3];
    const float* ldist = (const float*)d_in[4];
    const float* Wq = (const float*)d_in[5];
    const float* bq = (const float*)d_in[6];
    const float* Wk = (const float*)d_in[7];
    const float* bk = (const float*)d_in[8];
    const float* Wv = (const float*)d_in[9];
    const float* bv = (const float*)d_in[10];
    const float* Wo = (const float*)d_in[11];
    const float* bo = (const float*)d_in[12];
    const float* tbias = (const float*)d_in[13];

    float* out_attn  = (float*)d_out;                        // [B,S,E]
    float* out_probs = (float*)d_out + (size_t)B_ * S_ * E_; // [B,H,S,S]

    float* qg; cudaGetSymbolAddress((void**)&qg, g_Q);
    float* kg; cudaGetSymbolAddress((void**)&kg, g_K);
    float* vg; cudaGetSymbolAddress((void**)&vg, g_Vt);
    float* cg; cudaGetSymbolAddress((void**)&cg, g_ctx);

    const int M = B_ * S_;  // 4096

    tw_kernel<<<(S_ * S_ + 255) / 256, 256>>>(ldist);

    // projections
    dim3 gp(E_ / 128, M / 128);  // 4 x 32
    k_mm<2, 4, 128, 128, 0><<<gp, 256>>>(query, Wq, bq, qg, E_, E_, E_, 0, 0, nullptr, nullptr);
    k_mm<2, 4, 128, 128, 0><<<gp, 256>>>(key,   Wk, bk, kg, E_, E_, E_, 0, 0, nullptr, nullptr);
    k_mm<2, 4, 128, 128, 3><<<gp, 256>>>(value, Wv, bv, vg, E_, E_, E_, 0, 0, nullptr, nullptr);

    // scores: per bh, Q[bh] . K[bh]^T
    dim3 gs(S_ / 128, S_ / 128, B_ * H_);
    k_mm<2, 4, 128, 128, 2><<<gs, 256>>>(qg, kg, nullptr, out_probs, DH_, DH_, DH_,
                                         (long long)S_ * DH_, (long long)S_ * DH_,
                                         tmask, tbias);

    softmax_kernel<<<B_ * H_ * S_, 256>>>(out_probs);

    // ctx: P[bh] . Vt[bh]^T  (Vt is [d][s], so B operand rows are d, K-major in s)
    dim3 gc(1, S_ / 128, B_ * H_);
    k_mm<4, 2, 128, 64, 4><<<gc, 256>>>(out_probs, vg, nullptr, cg, S_, S_, S_,
                                        (long long)S_ * S_, (long long)DH_ * S_,
                                        nullptr, nullptr);

    // output projection
    k_mm<2, 4, 128, 128, 1><<<gp, 256>>>(cg, Wo, bo, out_attn, E_, E_, E_, 0, 0, nullptr, nullptr);
}

// round 3
// speedup vs baseline: 2.1543x; 1.5898x over previous
#include <cuda_runtime.h>
#include <cuda_bf16.h>
#include <math.h>
#include <stdint.h>

#define B_ 2
#define S_ 2048
#define E_ 512
#define H_ 8
#define DH_ 64
#define SCALE_ 0.125f  // 64^-0.5

#define BK 16          // fp32-equiv k per mainloop iter
#define SK 40          // smem row stride in bf16: 16 hi + 16 lo + 8 pad = 80B (odd mult of 16B)

typedef __nv_bfloat16 bf16;
typedef __nv_bfloat162 bf162;

// ---- scratch (device globals; allocation is forbidden) ----
__device__ bf16 g_qin_hi[4096 * 512], g_qin_lo[4096 * 512];
__device__ bf16 g_kin_hi[4096 * 512], g_kin_lo[4096 * 512];
__device__ bf16 g_vin_hi[4096 * 512], g_vin_lo[4096 * 512];
__device__ bf16 g_Wq_hi[512 * 512], g_Wq_lo[512 * 512];
__device__ bf16 g_Wk_hi[512 * 512], g_Wk_lo[512 * 512];
__device__ bf16 g_Wv_hi[512 * 512], g_Wv_lo[512 * 512];
__device__ bf16 g_Wo_hi[512 * 512], g_Wo_lo[512 * 512];
__device__ bf16 g_Q_hi[16 * 2048 * 64], g_Q_lo[16 * 2048 * 64];    // [bh][s][d]
__device__ bf16 g_K_hi[16 * 2048 * 64], g_K_lo[16 * 2048 * 64];    // [bh][s][d]
__device__ bf16 g_Vt_hi[16 * 64 * 2048], g_Vt_lo[16 * 64 * 2048];  // [bh][d][s]
__device__ bf16 g_P_hi[16ll * 2048 * 2048], g_P_lo[16ll * 2048 * 2048];
__device__ bf16 g_C_hi[4096 * 512], g_C_lo[4096 * 512];            // ctx [m][e]
__device__ float g_tw[S_ * S_];

// ---------------------------------------------------------------------------
__global__ void tw_kernel(const float* __restrict__ ld) {
    int i = blockIdx.x * blockDim.x + threadIdx.x;
    float4 v = ((const float4*)ld)[i];
    float4 o = make_float4(__expf(-v.x), __expf(-v.y), __expf(-v.z), __expf(-v.w));
    ((float4*)g_tw)[i] = o;
}

__global__ void split_kernel(const float* __restrict__ src, bf16* __restrict__ hi,
                             bf16* __restrict__ lo, int n4) {
    int i = blockIdx.x * blockDim.x + threadIdx.x;
    if (i >= n4) return;
    float4 v = ((const float4*)src)[i];
    bf16 h0 = __float2bfloat16(v.x), h1 = __float2bfloat16(v.y);
    bf16 h2 = __float2bfloat16(v.z), h3 = __float2bfloat16(v.w);
    ((bf162*)hi)[2 * i]     = __halves2bfloat162(h0, h1);
    ((bf162*)hi)[2 * i + 1] = __halves2bfloat162(h2, h3);
    ((bf162*)lo)[2 * i] = __halves2bfloat162(
        __float2bfloat16(v.x - __bfloat162float(h0)),
        __float2bfloat16(v.y - __bfloat162float(h1)));
    ((bf162*)lo)[2 * i + 1] = __halves2bfloat162(
        __float2bfloat16(v.z - __bfloat162float(h2)),
        __float2bfloat16(v.w - __bfloat162float(h3)));
}

// ---------------------------------------------------------------------------
__device__ __forceinline__ void ldsm4(uint32_t addr, uint32_t& r0, uint32_t& r1,
                                      uint32_t& r2, uint32_t& r3) {
    asm volatile("ldmatrix.sync.aligned.m8n8.x4.shared.b16 {%0,%1,%2,%3}, [%4];"
                 : "=r"(r0), "=r"(r1), "=r"(r2), "=r"(r3) : "r"(addr));
}

__device__ __forceinline__ void mma16816(float* c, const uint32_t* a, const uint32_t* b) {
    asm volatile(
        "mma.sync.aligned.m16n8k16.row.col.f32.bf16.bf16.f32 "
        "{%0,%1,%2,%3}, {%4,%5,%6,%7}, {%8,%9}, {%0,%1,%2,%3};\n"
        : "+f"(c[0]), "+f"(c[1]), "+f"(c[2]), "+f"(c[3])
        : "r"(a[0]), "r"(a[1]), "r"(a[2]), "r"(a[3]), "r"(b[0]), "r"(b[1]));
}

__device__ __forceinline__ void cpa16(uint32_t dst, const void* src) {
    asm volatile("cp.async.cg.shared.global [%0], [%1], 16;" :: "r"(dst), "l"(src));
}
__device__ __forceinline__ void cp_commit() { asm volatile("cp.async.commit_group;"); }
template <int N>
__device__ __forceinline__ void cp_wait() { asm volatile("cp.async.wait_group %0;" :: "n"(N)); }

// load one [ROWS x 16] hi+lo tile into smem stage (row layout [hi16|lo16|pad8])
template <int ROWS>
__device__ __forceinline__ void stage_load(const bf16* __restrict__ hi,
                                           const bf16* __restrict__ lo,
                                           int lda, int k0, uint32_t sdst, int tid) {
    #pragma unroll
    for (int i = 0; i < ROWS * 4 / 256; i++) {
        int idx = tid + i * 256;
        int r = idx >> 2, c = idx & 3;
        const bf16* src = ((c < 2) ? hi : lo) + (size_t)r * lda + k0 + (c & 1) * 8;
        uint32_t dst = sdst + (r * SK + ((c < 2) ? 0 : 16) + (c & 1) * 8) * 2;
        cpa16(dst, src);
    }
}

// ---------------------------------------------------------------------------
// D[M,N] = A . B^T in 3xBF16, double-buffered cp.async pipeline.
// MODE 0: epilogue writes split head layout [bh][s][d]   (Q/K projections)
// MODE 3: epilogue writes split transposed  [bh][d][s]   (V projection)
// MODE 4: epilogue writes split ctx [m][h*64+n]          (P.V)
// MODE 1: fp32 out [M,512] (+bias)                       (output projection)
// MODE 2: scores epilogue (scale, temporal bias, mask) -> fp32 P
// ---------------------------------------------------------------------------
template <int WARPS_M, int WARPS_N, int BM, int BN, int MODE>
__global__ __launch_bounds__(256) void k_mm(
    const bf16* __restrict__ Ahi, const bf16* __restrict__ Alo,
    const bf16* __restrict__ Bhi, const bf16* __restrict__ Blo,
    const float* __restrict__ bias, float* __restrict__ out,
    bf16* __restrict__ outHi, bf16* __restrict__ outLo,
    int K, int lda, int ldb, long long sAz, long long sBz,
    const int* __restrict__ mask, const float* __restrict__ tbias) {
    constexpr int WM = BM / WARPS_M;
    constexpr int WN = BN / WARPS_N;
    constexpr int MF = WM / 16;
    constexpr int NF = WN / 8;
    constexpr int STAGE = (BM + BN) * SK;   // bf16 elems per stage

    __shared__ bf16 smem[2 * STAGE];

    const int tid = threadIdx.x, wid = tid >> 5, lane = tid & 31;
    const int wm = wid % WARPS_M, wn = wid / WARPS_M;
    const int bz = blockIdx.z;
    const int m0 = blockIdx.y * BM, n0 = blockIdx.x * BN;

    const bf16* Ahp = Ahi + (long long)bz * sAz + (size_t)m0 * lda;
    const bf16* Alp = Alo + (long long)bz * sAz + (size_t)m0 * lda;
    const bf16* Bhp = Bhi + (long long)bz * sBz + (size_t)n0 * ldb;
    const bf16* Blp = Blo + (long long)bz * sBz + (size_t)n0 * ldb;

    float acc[MF][NF][4];
    #pragma unroll
    for (int i = 0; i < MF; i++)
        #pragma unroll
        for (int j = 0; j < NF; j++)
            #pragma unroll
            for (int q = 0; q < 4; q++) acc[i][j][q] = 0.f;

    const uint32_t sbase = (uint32_t)__cvta_generic_to_shared(smem);
    const int t8 = lane >> 3, r8 = lane & 7;
    const int frow = r8 + 8 * (t8 & 1);
    const int fcol = 8 * (t8 >> 1);

    const int niter = K / BK;
    // prologue: stage 0
    stage_load<BM>(Ahp, Alp, lda, 0, sbase, tid);
    stage_load<BN>(Bhp, Blp, ldb, 0, sbase + BM * SK * 2, tid);
    cp_commit();

    for (int it = 0; it < niter; it++) {
        if (it + 1 < niter) {
            uint32_t sd = sbase + ((it + 1) & 1) * STAGE * 2;
            stage_load<BM>(Ahp, Alp, lda, (it + 1) * BK, sd, tid);
            stage_load<BN>(Bhp, Blp, ldb, (it + 1) * BK, sd + BM * SK * 2, tid);
            cp_commit();
            cp_wait<1>();
        } else {
            cp_wait<0>();
        }
        __syncthreads();

        const uint32_t sA = sbase + (it & 1) * STAGE * 2;
        const uint32_t sB = sA + BM * SK * 2;
        #pragma unroll
        for (int p = 0; p < 3; p++) {
            const int ao = (p == 2) ? 16 : 0;
            const int bo = (p == 1) ? 16 : 0;
            uint32_t af[MF][4], bf[NF][2];
            #pragma unroll
            for (int mf = 0; mf < MF; mf++) {
                uint32_t addr = sA + ((wm * WM + mf * 16 + frow) * SK + ao + fcol) * 2;
                ldsm4(addr, af[mf][0], af[mf][1], af[mf][2], af[mf][3]);
            }
            #pragma unroll
            for (int nf2 = 0; nf2 < NF / 2; nf2++) {
                uint32_t r0, r1, r2, r3;
                uint32_t addr = sB + ((wn * WN + nf2 * 16 + frow) * SK + bo + fcol) * 2;
                ldsm4(addr, r0, r1, r2, r3);
                bf[2 * nf2][0] = r0;      bf[2 * nf2][1] = r2;
                bf[2 * nf2 + 1][0] = r1;  bf[2 * nf2 + 1][1] = r3;
            }
            #pragma unroll
            for (int mf = 0; mf < MF; mf++)
                #pragma unroll
                for (int nf = 0; nf < NF; nf++)
                    mma16816(acc[mf][nf], af[mf], bf[nf]);
        }
        __syncthreads();
    }

    // ---- epilogue ----
    const int lrow = lane >> 2, lcol = (lane & 3) * 2;
    #pragma unroll
    for (int mf = 0; mf < MF; mf++) {
        #pragma unroll
        for (int nf = 0; nf < NF; nf++) {
            #pragma unroll
            for (int hh = 0; hh < 2; hh++) {
                int m = m0 + wm * WM + mf * 16 + lrow + hh * 8;
                int n = n0 + wn * WN + nf * 8 + lcol;
                float v0 = acc[mf][nf][2 * hh];
                float v1 = acc[mf][nf][2 * hh + 1];
                if (MODE == 0) {  // split head layout [bh][s][d]
                    int b = m >> 11, s = m & 2047;
                    int h = n >> 6, d = n & 63;
                    size_t o = (((size_t)(b * H_ + h) * S_ + s) << 6) + d;
                    float x0 = v0 + bias[n], x1 = v1 + bias[n + 1];
                    bf16 h0 = __float2bfloat16(x0), h1 = __float2bfloat16(x1);
                    *(bf162*)&outHi[o] = __halves2bfloat162(h0, h1);
                    *(bf162*)&outLo[o] = __halves2bfloat162(
                        __float2bfloat16(x0 - __bfloat162float(h0)),
                        __float2bfloat16(x1 - __bfloat162float(h1)));
                } else if (MODE == 3) {  // split transposed [bh][d][s]
                    int b = m >> 11, s = m & 2047;
                    int h = n >> 6, d = n & 63;
                    size_t base = (size_t)(b * H_ + h) * DH_;
                    float x0 = v0 + bias[n], x1 = v1 + bias[n + 1];
                    bf16 h0 = __float2bfloat16(x0), h1 = __float2bfloat16(x1);
                    outHi[(base + d) * S_ + s] = h0;
                    outHi[(base + d + 1) * S_ + s] = h1;
                    outLo[(base + d) * S_ + s] = __float2bfloat16(x0 - __bfloat162float(h0));
                    outLo[(base + d + 1) * S_ + s] = __float2bfloat16(x1 - __bfloat162float(h1));
                } else if (MODE == 4) {  // split ctx [m][h*64+n]
                    int b = bz >> 3, h = bz & 7;
                    size_t o = ((size_t)b * S_ + m) * E_ + h * DH_ + n;
                    bf16 h0 = __float2bfloat16(v0), h1 = __float2bfloat16(v1);
                    *(bf162*)&outHi[o] = __halves2bfloat162(h0, h1);
                    *(bf162*)&outLo[o] = __halves2bfloat162(
                        __float2bfloat16(v0 - __bfloat162float(h0)),
                        __float2bfloat16(v1 - __bfloat162float(h1)));
                } else if (MODE == 1) {  // fp32 [M,512]
                    float2 val = make_float2(v0 + bias[n], v1 + bias[n + 1]);
                    *(float2*)&out[(size_t)m * 512 + n] = val;
                } else {  // MODE 2: scores
                    int h = bz & 7;
                    float tb = tbias[h];
                    size_t mn = (size_t)m * S_ + n;
                    float2 tw = *(const float2*)&g_tw[mn];
                    int2 mk = *(const int2*)&mask[mn];
                    float s0 = v0 * SCALE_ + tb * tw.x;
                    float s1 = v1 * SCALE_ + tb * tw.y;
                    if (mk.x == 0) s0 = -1e9f;
                    if (mk.y == 0) s1 = -1e9f;
                    *(float2*)&out[(size_t)bz * S_ * S_ + mn] = make_float2(s0, s1);
                }
            }
        }
    }
}

// ---------------------------------------------------------------------------
// in-place row softmax + split-bf16 emit, one block per row
// ---------------------------------------------------------------------------
__global__ void softmax_kernel(float* __restrict__ P) {
    const int tid = threadIdx.x;  // 256
    const size_t row = blockIdx.x;
    float* p = P + row * S_;
    bf16* phi = g_P_hi + row * S_;
    bf16* plo = g_P_lo + row * S_;
    __shared__ float red[256];

    float x[8];
    float mx = -INFINITY;
    #pragma unroll
    for (int i = 0; i < 8; i++) {
        x[i] = p[tid + i * 256];
        mx = fmaxf(mx, x[i]);
    }
    red[tid] = mx;
    __syncthreads();
    for (int s = 128; s > 0; s >>= 1) {
        if (tid < s) red[tid] = fmaxf(red[tid], red[tid + s]);
        __syncthreads();
    }
    mx = red[0];
    __syncthreads();

    float sum = 0.f;
    #pragma unroll
    for (int i = 0; i < 8; i++) {
        x[i] = __expf(x[i] - mx);
        sum += x[i];
    }
    red[tid] = sum;
    __syncthreads();
    for (int s = 128; s > 0; s >>= 1) {
        if (tid < s) red[tid] += red[tid + s];
        __syncthreads();
    }
    float inv = 1.0f / red[0];
    #pragma unroll
    for (int i = 0; i < 8; i++) {
        float v = x[i] * inv;
        int c = tid + i * 256;
        p[c] = v;
        bf16 h = __float2bfloat16(v);
        phi[c] = h;
        plo[c] = __float2bfloat16(v - __bfloat162float(h));
    }
}

// ---------------------------------------------------------------------------
#define SYM(p, s) cudaGetSymbolAddress((void**)&p, s)

extern "C" void kernel_launch(void* const* d_in, const int* in_sizes, int n_in,
                              void* d_out, int out_size) {
    const float* query = (const float*)d_in[0];
    const float* key   = (const float*)d_in[1];
    const float* value = (const float*)d_in[2];
    const int*   tmask = (const int*)d_in[3];
    const float* ldist = (const float*)d_in[4];
    const float* Wq = (const float*)d_in[5];
    const float* bq = (const float*)d_in[6];
    const float* Wk = (const float*)d_in[7];
    const float* bk = (const float*)d_in[8];
    const float* Wv = (const float*)d_in[9];
    const float* bv = (const float*)d_in[10];
    const float* Wo = (const float*)d_in[11];
    const float* bo = (const float*)d_in[12];
    const float* tbias = (const float*)d_in[13];

    float* out_attn  = (float*)d_out;
    float* out_probs = (float*)d_out + (size_t)B_ * S_ * E_;

    bf16 *qih, *qil, *kih, *kil, *vih, *vil;
    bf16 *wqh, *wql, *wkh, *wkl, *wvh, *wvl, *woh, *wol;
    bf16 *Qh, *Ql, *Kh, *Kl, *Vh, *Vl, *Ph, *Pl, *Ch, *Cl;
    SYM(qih, g_qin_hi); SYM(qil, g_qin_lo);
    SYM(kih, g_kin_hi); SYM(kil, g_kin_lo);
    SYM(vih, g_vin_hi); SYM(vil, g_vin_lo);
    SYM(wqh, g_Wq_hi); SYM(wql, g_Wq_lo);
    SYM(wkh, g_Wk_hi); SYM(wkl, g_Wk_lo);
    SYM(wvh, g_Wv_hi); SYM(wvl, g_Wv_lo);
    SYM(woh, g_Wo_hi); SYM(wol, g_Wo_lo);
    SYM(Qh, g_Q_hi); SYM(Ql, g_Q_lo);
    SYM(Kh, g_K_hi); SYM(Kl, g_K_lo);
    SYM(Vh, g_Vt_hi); SYM(Vl, g_Vt_lo);
    SYM(Ph, g_P_hi); SYM(Pl, g_P_lo);
    SYM(Ch, g_C_hi); SYM(Cl, g_C_lo);

    const int M = B_ * S_;  // 4096

    // preprocessing
    tw_kernel<<<(S_ * S_ / 4) / 256, 256>>>(ldist);
    split_kernel<<<2048, 256>>>(query, qih, qil, M * E_ / 4);
    split_kernel<<<2048, 256>>>(key,   kih, kil, M * E_ / 4);
    split_kernel<<<2048, 256>>>(value, vih, vil, M * E_ / 4);
    split_kernel<<<256, 256>>>(Wq, wqh, wql, E_ * E_ / 4);
    split_kernel<<<256, 256>>>(Wk, wkh, wkl, E_ * E_ / 4);
    split_kernel<<<256, 256>>>(Wv, wvh, wvl, E_ * E_ / 4);
    split_kernel<<<256, 256>>>(Wo, woh, wol, E_ * E_ / 4);

    // projections (write split head layouts)
    dim3 gp(E_ / 128, M / 128);
    k_mm<2, 4, 128, 128, 0><<<gp, 256>>>(qih, qil, wqh, wql, bq, nullptr, Qh, Ql,
                                         E_, E_, E_, 0, 0, nullptr, nullptr);
    k_mm<2, 4, 128, 128, 0><<<gp, 256>>>(kih, kil, wkh, wkl, bk, nullptr, Kh, Kl,
                                         E_, E_, E_, 0, 0, nullptr, nullptr);
    k_mm<2, 4, 128, 128, 3><<<gp, 256>>>(vih, vil, wvh, wvl, bv, nullptr, Vh, Vl,
                                         E_, E_, E_, 0, 0, nullptr, nullptr);

    // scores
    dim3 gs(S_ / 128, S_ / 128, B_ * H_);
    k_mm<2, 4, 128, 128, 2><<<gs, 256>>>(Qh, Ql, Kh, Kl, nullptr, out_probs, nullptr, nullptr,
                                         DH_, DH_, DH_, (long long)S_ * DH_, (long long)S_ * DH_,
                                         tmask, tbias);

    softmax_kernel<<<B_ * H_ * S_, 256>>>(out_probs);

    // ctx = P.Vt^T  -> split ctx
    dim3 gc(1, S_ / 128, B_ * H_);
    k_mm<4, 2, 128, 64, 4><<<gc, 256>>>(Ph, Pl, Vh, Vl, nullptr, nullptr, Ch, Cl,
                                        S_, S_, S_, (long long)S_ * S_, (long long)DH_ * S_,
                                        nullptr, nullptr);

    // output projection
    k_mm<2, 4, 128, 128, 1><<<gp, 256>>>(Ch, Cl, woh, wol, bo, out_attn, nullptr, nullptr,
                                         E_, E_, E_, 0, 0, nullptr, nullptr);
}